// round 6
// baseline (speedup 1.0000x reference)
#include <cuda_runtime.h>

// reshape_78271484002964: [16,64,256,256] f32, SPLIT=(2,16,16), map_type=1.
// out[b,i,j,k,cc,hh,ww] = in[b,i,cc,j,hh,k,ww]
// sizes: b=16, i=2, j=16, k=16, cc=32, hh=16, ww=16.
//
// float4-unit index bit maps (24 bits total).
// Output g (fast->slow): ww4 [0,2) | hh [2,6) | cc [6,11) | k [11,15)
//                         | j [15,19) | i bit19 | b [20,24)
// Input  (fast->slow):    ww4 [0,2) | k [2,6)  | hh [6,10) | j [10,14)
//                         | cc [14,19) | i bit19 | b [20,24)
//
// R5: smem-staged tile. Tile = output bits {0-6, 11-14} = 2048 float4 = 32KB.
// Image in input space = bits {0-9} + bit 14 = two contiguous 16KB runs.
// -> phase 1 loads fully coalesced (contiguous), phase 2 stores fully
// coalesced (16 x 2KB runs). XOR swizzle (bit7 -> bit2) makes both the
// permuted smem stores and linear smem loads bank-conflict-free per
// quarter-warp phase.
//
// Tile-local maps:
//   m (input-local, 11b):  ww4 [0,2) | k [2,6) | hh [6,10) | cc0 bit10
//   l (output-local, 11b): ww4 [0,2) | hh [2,6) | cc0 bit6 | k [7,11)
//   l = (m&3) | ((m>>6 & 15)<<2) | ((m>>10 & 1)<<6) | ((m>>2 & 15)<<7)

__global__ void __launch_bounds__(256)
reshape_78271484002964_kernel(const float4* __restrict__ in,
                              float4* __restrict__ out) {
    __shared__ float4 tile[2048];

    const unsigned bk  = blockIdx.x;            // 13 bits
    const unsigned tid = threadIdx.x;           // 8 bits

    // Tile-base bits. Output base: cc[1..4] -> out [7,11); rest -> out [15,24).
    const unsigned outBase = ((bk & 15u) << 7) | ((bk >> 4) << 15);
    // Input base: cc[1..4] -> in [15,19); j -> in [10,14); i,b -> [19,24).
    const unsigned inBase  = ((bk & 15u) << 15)
                           | (((bk >> 4) & 15u) << 10)
                           | ((bk >> 8) << 19);

    // ---- Phase 1: contiguous global loads -> permuted smem stores ----
    float4 v[8];
#pragma unroll
    for (int q = 0; q < 8; q++) {
        unsigned m = q * 256u + tid;
        unsigned in_addr = inBase | (m & 0x3FFu) | ((m >> 10) << 14);
        v[q] = __ldcs(in + in_addr);
    }
#pragma unroll
    for (int q = 0; q < 8; q++) {
        unsigned m = q * 256u + tid;
        unsigned l = (m & 3u)
                   | (((m >> 6) & 15u) << 2)
                   | (((m >> 10) & 1u) << 6)
                   | (((m >> 2) & 15u) << 7);
        tile[l ^ ((l >> 5) & 4u)] = v[q];
    }

    __syncthreads();

    // ---- Phase 2: linear smem loads -> contiguous global stores ----
#pragma unroll
    for (int q = 0; q < 8; q++) {
        unsigned l = q * 256u + tid;
        unsigned g = outBase | (l & 0x7Fu) | ((l >> 7) << 11);
        __stcs(out + g, tile[l ^ ((l >> 5) & 4u)]);
    }
}

extern "C" void kernel_launch(void* const* d_in, const int* in_sizes, int n_in,
                              void* d_out, int out_size) {
    const float4* in  = (const float4*)d_in[0];
    float4*       out = (float4*)d_out;
    // 16,777,216 float4 / 2048 per tile = 8192 blocks
    reshape_78271484002964_kernel<<<8192, 256>>>(in, out);
}

// round 7
// speedup vs baseline: 1.1495x; 1.1495x over previous
#include <cuda_runtime.h>

// reshape_78271484002964: [16,64,256,256] f32, SPLIT=(2,16,16), map_type=1.
// out[b,i,j,k,cc,hh,ww] = in[b,i,cc,j,hh,k,ww]
// sizes: b=16, i=2, j=16, k=16, cc=32, hh=16, ww=16.
//
// float4-unit bit map. Output float4 index g (fast->slow):
//   ww4 [0,2) | hh [2,6) | cc [6,11) | k [11,15) | j [15,19) | i 19 | b [20,24)
// Input float4 strides: ww4=1, k=1<<2, hh=1<<6, j=1<<10, cc=1<<14,
//   bits >= 19 (i,b) pass through unchanged.
//
// R7: direct copy, 8 float4 per thread. Block tile = 2048 float4; per-thread
// elements stride 256 in output, which varies only g bits 8-10 (cc[2..4])
// -> input addresses are base + q*(1<<16). One bit-shuffle per thread,
// 8 independent loads (MLP=8), 8 coalesced stores. Streaming hints
// (single-touch data).

__device__ __forceinline__ unsigned out_to_in(unsigned g) {
    return  (g & 3u)                      // ww4
         | (((g >> 11) & 15u) << 2)       // k
         | (((g >> 2)  & 15u) << 6)       // hh
         | (((g >> 15) & 15u) << 10)      // j
         | (((g >> 6)  & 31u) << 14)      // cc
         |  (g & 0xFFF80000u);            // i, b pass through
}

__global__ void __launch_bounds__(256)
reshape_78271484002964_kernel(const float4* __restrict__ in,
                              float4* __restrict__ out) {
    const unsigned g0  = blockIdx.x * 2048u + threadIdx.x;
    const unsigned in0 = out_to_in(g0);

    float4 v[8];
#pragma unroll
    for (int q = 0; q < 8; q++)
        v[q] = __ldcs(in + in0 + (unsigned)q * 65536u);

#pragma unroll
    for (int q = 0; q < 8; q++)
        __stcs(out + g0 + (unsigned)q * 256u, v[q]);
}

extern "C" void kernel_launch(void* const* d_in, const int* in_sizes, int n_in,
                              void* d_out, int out_size) {
    const float4* in  = (const float4*)d_in[0];
    float4*       out = (float4*)d_out;
    // 16,777,216 float4 / 2048 per block = 8192 blocks
    reshape_78271484002964_kernel<<<8192, 256>>>(in, out);
}

// round 8
// speedup vs baseline: 1.1531x; 1.0031x over previous
#include <cuda_runtime.h>

// reshape_78271484002964: [16,64,256,256] f32, SPLIT=(2,16,16), map_type=1.
// out[b,i,j,k,cc,hh,ww] = in[b,i,cc,j,hh,k,ww]
// sizes: b=16, i=2, j=16, k=16, cc=32, hh=16, ww=16.
//
// float4-unit bit maps (24 bits).
// Input m (fast->slow):  ww4 [0,2) | k [2,6) | hh [6,10) | j [10,14)
//                        | cc [14,19) | i 19 | b [20,24)
// Output g (fast->slow): ww4 [0,2) | hh [2,6) | cc [6,11) | k [11,15)
//                        | j [15,19) | i 19 | b [20,24)
//
// R8: iterate in INPUT order. Loads are perfectly contiguous per warp
// (512 B streaming; loads are the latency-critical side). Stores scatter in
// 64 B chunks but are posted (no warp stall); adjacent line-halves are
// written by neighboring warps of the same block -> L2 merges to full-line
// writebacks. 8 float4 per thread, per-thread input stride 256:
// m bits 8,9 = hh[2..3] -> out stride 16; m bit 10 = j[0] -> out stride 32768.

__device__ __forceinline__ unsigned in_to_out(unsigned m) {
    return  (m & 3u)                      // ww4
         | (((m >> 6)  & 15u) << 2)       // hh
         | (((m >> 14) & 31u) << 6)       // cc
         | (((m >> 2)  & 15u) << 11)      // k
         | (((m >> 10) & 15u) << 15)      // j
         |  (m & 0xFFF80000u);            // i, b pass through
}

__global__ void __launch_bounds__(256)
reshape_78271484002964_kernel(const float4* __restrict__ in,
                              float4* __restrict__ out) {
    const unsigned m0   = blockIdx.x * 2048u + threadIdx.x;
    const unsigned out0 = in_to_out(m0);

    float4 v[8];
#pragma unroll
    for (int q = 0; q < 8; q++)
        v[q] = __ldcs(in + m0 + (unsigned)q * 256u);

#pragma unroll
    for (int q = 0; q < 8; q++)
        __stcs(out + out0 + (unsigned)(q & 3) * 16u
                          + (unsigned)(q >> 2) * 32768u, v[q]);
}

extern "C" void kernel_launch(void* const* d_in, const int* in_sizes, int n_in,
                              void* d_out, int out_size) {
    const float4* in  = (const float4*)d_in[0];
    float4*       out = (float4*)d_out;
    // 16,777,216 float4 / 2048 per block = 8192 blocks
    reshape_78271484002964_kernel<<<8192, 256>>>(in, out);
}